// round 3
// baseline (speedup 1.0000x reference)
#include <cuda_runtime.h>
#include <cstdint>
#include <cstddef>

#define BB 4
#define NN 512
#define FF 16
#define EE 64

#define THREADS 128
#define WARPS 4
#define ROWS_PER_BLOCK 4     // 1 row per warp
#define TJ 32                // j-tile per stage
#define NTILES (NN / TJ)     // 16

#define LR_A 0.505f
#define LR_B 0.495f

typedef unsigned long long u64;

__device__ __forceinline__ u64 ffma2(u64 a, u64 b, u64 c) {
    u64 d;
    asm("fma.rn.f32x2 %0, %1, %2, %3;" : "=l"(d) : "l"(a), "l"(b), "l"(c));
    return d;
}
__device__ __forceinline__ void upk2(u64 v, float& lo, float& hi) {
    asm("mov.b64 {%0, %1}, %2;" : "=f"(lo), "=f"(hi) : "l"(v));
}
__device__ __forceinline__ unsigned smem_u32(const void* p) {
    unsigned r;
    asm("{ .reg .u64 t; cvta.to.shared.u64 t, %1; cvt.u32.u64 %0, t; }"
        : "=r"(r) : "l"(p));
    return r;
}
__device__ __forceinline__ void cp16(unsigned d, const void* s) {
    asm volatile("cp.async.cg.shared.global [%0], [%1], 16;" :: "r"(d), "l"(s));
}
__device__ __forceinline__ void cp4(unsigned d, const void* s) {
    asm volatile("cp.async.ca.shared.global [%0], [%1], 4;" :: "r"(d), "l"(s));
}
__device__ __forceinline__ void cpcommit() {
    asm volatile("cp.async.commit_group;" ::: "memory");
}
template <int N>
__device__ __forceinline__ void cpwait() {
    asm volatile("cp.async.wait_group %0;" :: "n"(N) : "memory");
}

__global__ void __launch_bounds__(THREADS, 4)
edge_embed_kernel(const float* __restrict__ edge,
                  const float* __restrict__ adj,
                  const float* __restrict__ w4,
                  const float* __restrict__ w3,
                  float* __restrict__ out)
{
    // Per-warp double-buffered edge tile, transposed: [warp][buf][ff2][j] (16B units)
    __shared__ ulonglong2 bufe[WARPS][2][4][TJ];   // 4*2*4*32*16 = 16 KB
    __shared__ float      bufa[WARPS][2][TJ];      // 1 KB
    __shared__ float      sums[WARPS][EE];         // 1 KB

    const int tid  = threadIdx.x;
    const int warp = tid >> 5;
    const int lane = tid & 31;
    const int row  = blockIdx.x * ROWS_PER_BLOCK + warp;   // b*N + i

    const float* erow = edge + (size_t)row * (NN * FF);
    const float* arow = adj  + (size_t)row * NN;

    // w4 rows for this lane's two e's, as f-pairs (natural layout)
    const ulonglong2* w4v = reinterpret_cast<const ulonglong2*>(w4);
    ulonglong2 w40[4], w41[4];   // e0 = lane, e1 = lane + 32; 16 u64 total
#pragma unroll
    for (int k = 0; k < 4; ++k) {
        w40[k] = __ldg(w4v + lane * 4 + k);
        w41[k] = __ldg(w4v + (lane + 32) * 4 + k);
    }

    // ---- prefetch tile 0 ----
    {
        const float* src = erow + (size_t)lane * FF;   // j = lane
#pragma unroll
        for (int k = 0; k < 4; ++k)
            cp16(smem_u32(&bufe[warp][0][k][lane]), src + 4 * k);
        cp4(smem_u32(&bufa[warp][0][lane]), arow + lane);
        cpcommit();
    }

    float acc0 = 0.0f, acc1 = 0.0f;

    for (int t = 0; t < NTILES; ++t) {
        const int b = t & 1;
        if (t + 1 < NTILES) {
            const int nb = (t + 1) & 1;
            const float* src = erow + (size_t)((t + 1) * TJ + lane) * FF;
#pragma unroll
            for (int k = 0; k < 4; ++k)
                cp16(smem_u32(&bufe[warp][nb][k][lane]), src + 4 * k);
            cp4(smem_u32(&bufa[warp][nb][lane]), arow + (t + 1) * TJ + lane);
            cpcommit();
            cpwait<1>();
        } else {
            cpwait<0>();
        }
        __syncwarp();

#pragma unroll 4
        for (int jj = 0; jj < TJ; ++jj) {
            ulonglong2 q0 = bufe[warp][b][0][jj];   // broadcast LDS.128
            ulonglong2 q1 = bufe[warp][b][1][jj];
            ulonglong2 q2 = bufe[warp][b][2][jj];
            ulonglong2 q3 = bufe[warp][b][3][jj];
            float a = bufa[warp][b][jj];

            u64 s0 = 0ULL, s1 = 0ULL;
            s0 = ffma2(w40[0].x, q0.x, s0);  s1 = ffma2(w41[0].x, q0.x, s1);
            s0 = ffma2(w40[0].y, q0.y, s0);  s1 = ffma2(w41[0].y, q0.y, s1);
            s0 = ffma2(w40[1].x, q1.x, s0);  s1 = ffma2(w41[1].x, q1.x, s1);
            s0 = ffma2(w40[1].y, q1.y, s0);  s1 = ffma2(w41[1].y, q1.y, s1);
            s0 = ffma2(w40[2].x, q2.x, s0);  s1 = ffma2(w41[2].x, q2.x, s1);
            s0 = ffma2(w40[2].y, q2.y, s0);  s1 = ffma2(w41[2].y, q2.y, s1);
            s0 = ffma2(w40[3].x, q3.x, s0);  s1 = ffma2(w41[3].x, q3.x, s1);
            s0 = ffma2(w40[3].y, q3.y, s0);  s1 = ffma2(w41[3].y, q3.y, s1);

            float s0lo, s0hi, s1lo, s1hi;
            upk2(s0, s0lo, s0hi);
            upk2(s1, s1lo, s1hi);
            const float v0 = s0lo + s0hi;       // full dot for e0
            const float v1 = s1lo + s1hi;       // full dot for e1
            const float aA = a * LR_A;
            const float aB = a * LR_B;
            acc0 = fmaf(aA, v0, fmaf(aB, fabsf(v0), acc0));
            acc1 = fmaf(aA, v1, fmaf(aB, fabsf(v1), acc1));
        }
        __syncwarp();   // tile buffer b is free for the prefetch issued next iter
    }

    // S[e] is distributed: lane holds e=lane, e=lane+32
    sums[warp][lane]      = acc0;
    sums[warp][lane + 32] = acc1;
    __syncwarp();

    // theta3: out[row][o] = sum_e S[e] * w3[o][e]; lane handles o=lane, o=lane+32
    const float* srow = sums[warp];
    const float4* w3v = reinterpret_cast<const float4*>(w3);
    float o0 = 0.0f, o1 = 0.0f;
#pragma unroll
    for (int k = 0; k < 16; ++k) {
        float4 wa = __ldg(w3v + lane * 16 + k);          // w3[lane][4k..4k+3]
        float4 wb = __ldg(w3v + (lane + 32) * 16 + k);   // w3[lane+32][...]
        float e0 = srow[4 * k + 0], e1 = srow[4 * k + 1];
        float e2 = srow[4 * k + 2], e3 = srow[4 * k + 3];
        o0 = fmaf(wa.x, e0, o0); o0 = fmaf(wa.y, e1, o0);
        o0 = fmaf(wa.z, e2, o0); o0 = fmaf(wa.w, e3, o0);
        o1 = fmaf(wb.x, e0, o1); o1 = fmaf(wb.y, e1, o1);
        o1 = fmaf(wb.z, e2, o1); o1 = fmaf(wb.w, e3, o1);
    }
    out[(size_t)row * EE + lane]      = o0;
    out[(size_t)row * EE + 32 + lane] = o1;
}

extern "C" void kernel_launch(void* const* d_in, const int* in_sizes, int n_in,
                              void* d_out, int out_size) {
    const float* edge = (const float*)d_in[0];   // (4,512,512,16) f32
    const float* adj  = (const float*)d_in[1];   // (4,512,512)    f32
    const float* w4   = (const float*)d_in[2];   // (64,16)        f32
    const float* w3   = (const float*)d_in[3];   // (64,64)        f32
    float* out = (float*)d_out;                  // (4,512,64)     f32

    dim3 grid((BB * NN) / ROWS_PER_BLOCK);       // 512 blocks
    edge_embed_kernel<<<grid, THREADS>>>(edge, adj, w4, w3, out);
}

// round 6
// speedup vs baseline: 1.6791x; 1.6791x over previous
#include <cuda_runtime.h>
#include <cstdint>
#include <cstddef>

#define BB 4
#define NN 512
#define FF 16
#define EE 64
#define THREADS 128
#define STRIDE 20            // padded floats per E row (bank-conflict-free LDS)

#define LR_A 0.505f
#define LR_B 0.495f

typedef unsigned long long u64;
typedef unsigned int u32;

__device__ __forceinline__ u64 pk2(float lo, float hi) {
    u64 d; asm("mov.b64 %0, {%1, %2};" : "=l"(d) : "f"(lo), "f"(hi)); return d;
}
__device__ __forceinline__ void upk2(u64 v, float& lo, float& hi) {
    asm("mov.b64 {%0, %1}, %2;" : "=f"(lo), "=f"(hi) : "l"(v));
}
__device__ __forceinline__ u64 ffma2(u64 a, u64 b, u64 c) {
    u64 d; asm("fma.rn.f32x2 %0, %1, %2, %3;" : "=l"(d) : "l"(a), "l"(b), "l"(c)); return d;
}
__device__ __forceinline__ unsigned smem_u32(const void* p) {
    unsigned r;
    asm("{ .reg .u64 t; cvta.to.shared.u64 t, %1; cvt.u32.u64 %0, t; }" : "=r"(r) : "l"(p));
    return r;
}
__device__ __forceinline__ void cp16(unsigned d, const void* s) {
    asm volatile("cp.async.cg.shared.global [%0], [%1], 16;" :: "r"(d), "l"(s));
}
__device__ __forceinline__ void cpcommit() { asm volatile("cp.async.commit_group;" ::: "memory"); }
template <int N> __device__ __forceinline__ void cpwait() {
    asm volatile("cp.async.wait_group %0;" :: "n"(N) : "memory");
}
__device__ __forceinline__ u32 tf32u(float x) {
    u32 r; asm("cvt.rna.tf32.f32 %0, %1;" : "=r"(r) : "f"(x)); return r;
}
// D(m16n8) += A(m16k8,tf32) * B(k8n8,tf32)
__device__ __forceinline__ void mma8(float d[4], const u32 a[4], const u32 b[2]) {
    asm volatile("mma.sync.aligned.m16n8k8.row.col.f32.tf32.tf32.f32 "
        "{%0,%1,%2,%3}, {%4,%5,%6,%7}, {%8,%9}, {%0,%1,%2,%3};"
        : "+f"(d[0]), "+f"(d[1]), "+f"(d[2]), "+f"(d[3])
        : "r"(a[0]), "r"(a[1]), "r"(a[2]), "r"(a[3]), "r"(b[0]), "r"(b[1]));
}

__global__ void __launch_bounds__(THREADS, 4)
edge_embed_mma_kernel(const float* __restrict__ edge,
                      const float* __restrict__ adj,
                      const float* __restrict__ w4,
                      const float* __restrict__ w3,
                      float* __restrict__ out)
{
    __shared__ float Es[NN * STRIDE];   // 40 KB, padded rows
    __shared__ float adj_s[NN];         // 2 KB
    __shared__ float Sp[4][EE];         // per-warp partials
    __shared__ float Sh[EE];

    const int tid  = threadIdx.x;
    const int lane = tid & 31;
    const int warp = tid >> 5;
    const int gid  = lane >> 2;         // 0..7
    const int tig  = lane & 3;          // 0..3
    const int row  = blockIdx.x;        // b*N + i

    const float* erow = edge + (size_t)row * (NN * FF);
    const float* arow = adj  + (size_t)row * NN;

    // ---- async stage: whole E row (padded) + adj row ----
    for (int c = tid; c < NN * 4; c += THREADS) {
        int r = c >> 2, k = c & 3;
        cp16(smem_u32(&Es[r * STRIDE + k * 4]), erow + r * 16 + k * 4);
    }
    cp16(smem_u32(&adj_s[tid * 4]), arow + tid * 4);
    cpcommit();

    // ---- W4 fragments in registers, 3xTF32 split ----
    // B[k][n]: b0 = W[n0+gid][k0+tig], b1 = W[n0+gid][k0+tig+4]
    u32 Wb[2][8][2], Ws[2][8][2];
#pragma unroll
    for (int k = 0; k < 2; ++k) {
#pragma unroll
        for (int nt = 0; nt < 8; ++nt) {
            float w0 = __ldg(w4 + (nt * 8 + gid) * FF + k * 8 + tig);
            float w1 = __ldg(w4 + (nt * 8 + gid) * FF + k * 8 + tig + 4);
            u32 b0 = tf32u(w0);
            u32 b1 = tf32u(w1);
            Wb[k][nt][0] = b0;
            Wb[k][nt][1] = b1;
            Ws[k][nt][0] = tf32u(w0 - __uint_as_float(b0));
            Ws[k][nt][1] = tf32u(w1 - __uint_as_float(b1));
        }
    }

    u64 acc2[8];
#pragma unroll
    for (int i = 0; i < 8; ++i) acc2[i] = 0ULL;
    const u64 ABS2 = 0x7FFFFFFF7FFFFFFFULL;

    cpwait<0>();
    __syncthreads();

    // ---- main loop: 8 m-tiles (16 j each) per warp ----
#pragma unroll 2
    for (int i = 0; i < 8; ++i) {
        const int j0 = (warp * 8 + i) * 16;

        // A fragments for both k-tiles, split big/small
        u32 Ab[2][4], As[2][4];
#pragma unroll
        for (int k = 0; k < 2; ++k) {
            const int base0 = (j0 + gid) * STRIDE + k * 8;
            const int base1 = (j0 + gid + 8) * STRIDE + k * 8;
            float x0 = Es[base0 + tig];
            float x1 = Es[base1 + tig];
            float x2 = Es[base0 + tig + 4];
            float x3 = Es[base1 + tig + 4];
            u32 h0 = tf32u(x0), h1 = tf32u(x1), h2 = tf32u(x2), h3 = tf32u(x3);
            Ab[k][0] = h0; Ab[k][1] = h1; Ab[k][2] = h2; Ab[k][3] = h3;
            As[k][0] = tf32u(x0 - __uint_as_float(h0));
            As[k][1] = tf32u(x1 - __uint_as_float(h1));
            As[k][2] = tf32u(x2 - __uint_as_float(h2));
            As[k][3] = tf32u(x3 - __uint_as_float(h3));
        }

        const float aj0 = adj_s[j0 + gid];
        const float aj1 = adj_s[j0 + gid + 8];
        const u64 A0 = pk2(aj0 * LR_A, aj0 * LR_A);
        const u64 B0 = pk2(aj0 * LR_B, aj0 * LR_B);
        const u64 A1 = pk2(aj1 * LR_A, aj1 * LR_A);
        const u64 B1 = pk2(aj1 * LR_B, aj1 * LR_B);

#pragma unroll
        for (int nt = 0; nt < 8; ++nt) {
            float d[4] = {0.f, 0.f, 0.f, 0.f};
#pragma unroll
            for (int k = 0; k < 2; ++k) {
                mma8(d, Ab[k], Wb[k][nt]);   // big * big
                mma8(d, As[k], Wb[k][nt]);   // small * big
                mma8(d, Ab[k], Ws[k][nt]);   // big * small
            }
            // d0,d1 -> (j0+gid, e=8nt+2tig{,+1}); d2,d3 -> (j0+gid+8, same e)
            u64 v01 = pk2(d[0], d[1]);
            u64 v23 = pk2(d[2], d[3]);
            acc2[nt] = ffma2(A0, v01,        acc2[nt]);
            acc2[nt] = ffma2(B0, v01 & ABS2, acc2[nt]);
            acc2[nt] = ffma2(A1, v23,        acc2[nt]);
            acc2[nt] = ffma2(B1, v23 & ABS2, acc2[nt]);
        }
    }

    // ---- reduce over gid (lanes differing by multiples of 4) ----
    float accf[16];
#pragma unroll
    for (int nt = 0; nt < 8; ++nt) upk2(acc2[nt], accf[2 * nt], accf[2 * nt + 1]);
#pragma unroll
    for (int off = 16; off >= 4; off >>= 1) {
#pragma unroll
        for (int i = 0; i < 16; ++i)
            accf[i] += __shfl_down_sync(0xFFFFFFFFu, accf[i], off);
    }
    if (lane < 4) {
#pragma unroll
        for (int nt = 0; nt < 8; ++nt) {
            Sp[warp][nt * 8 + 2 * lane]     = accf[2 * nt];
            Sp[warp][nt * 8 + 2 * lane + 1] = accf[2 * nt + 1];
        }
    }
    __syncthreads();

    if (tid < EE) {
        Sh[tid] = Sp[0][tid] + Sp[1][tid] + Sp[2][tid] + Sp[3][tid];
    }
    __syncthreads();

    // ---- theta3: out[row][o] = sum_e S[e] * w3[o][e] ----
    if (tid < EE) {
        const float4* w3v = reinterpret_cast<const float4*>(w3 + tid * EE);
        float o = 0.0f;
#pragma unroll
        for (int k = 0; k < 16; ++k) {
            float4 w = __ldg(w3v + k);
            o = fmaf(w.x, Sh[4 * k + 0], o);
            o = fmaf(w.y, Sh[4 * k + 1], o);
            o = fmaf(w.z, Sh[4 * k + 2], o);
            o = fmaf(w.w, Sh[4 * k + 3], o);
        }
        out[(size_t)row * EE + tid] = o;
    }
}

extern "C" void kernel_launch(void* const* d_in, const int* in_sizes, int n_in,
                              void* d_out, int out_size) {
    const float* edge = (const float*)d_in[0];   // (4,512,512,16) f32
    const float* adj  = (const float*)d_in[1];   // (4,512,512)    f32
    const float* w4   = (const float*)d_in[2];   // (64,16)        f32
    const float* w3   = (const float*)d_in[3];   // (64,64)        f32
    float* out = (float*)d_out;                  // (4,512,64)     f32

    edge_embed_mma_kernel<<<BB * NN, THREADS>>>(edge, adj, w4, w3, out);
}

// round 7
// speedup vs baseline: 2.5738x; 1.5328x over previous
#include <cuda_runtime.h>
#include <cstdint>
#include <cstddef>

#define BB 4
#define NN 512
#define FF 16
#define EE 64
#define THREADS 128

#define LR_A 0.505f
#define LR_B 0.495f

typedef unsigned long long u64;
typedef unsigned int u32;

__device__ __forceinline__ u64 pk2(float lo, float hi) {
    u64 d; asm("mov.b64 %0, {%1, %2};" : "=l"(d) : "f"(lo), "f"(hi)); return d;
}
__device__ __forceinline__ void upk2(u64 v, float& lo, float& hi) {
    asm("mov.b64 {%0, %1}, %2;" : "=f"(lo), "=f"(hi) : "l"(v));
}
__device__ __forceinline__ u64 ffma2(u64 a, u64 b, u64 c) {
    u64 d; asm("fma.rn.f32x2 %0, %1, %2, %3;" : "=l"(d) : "l"(a), "l"(b), "l"(c)); return d;
}
__device__ __forceinline__ unsigned smem_u32(const void* p) {
    unsigned r;
    asm("{ .reg .u64 t; cvta.to.shared.u64 t, %1; cvt.u32.u64 %0, t; }" : "=r"(r) : "l"(p));
    return r;
}
__device__ __forceinline__ void cp16(unsigned d, const void* s) {
    asm volatile("cp.async.cg.shared.global [%0], [%1], 16;" :: "r"(d), "l"(s));
}
__device__ __forceinline__ void cpcommit() { asm volatile("cp.async.commit_group;" ::: "memory"); }
template <int N> __device__ __forceinline__ void cpwait() {
    asm volatile("cp.async.wait_group %0;" :: "n"(N) : "memory");
}

// pack two f32 -> bf16x2 (lo in low half = smaller k index)
__device__ __forceinline__ u32 pk_bf16(float lo, float hi) {
    u32 d; asm("cvt.rn.bf16x2.f32 %0, %1, %2;" : "=r"(d) : "f"(hi), "f"(lo)); return d;
}
__device__ __forceinline__ float bf_lo(u32 p) { return __uint_as_float(p << 16); }
__device__ __forceinline__ float bf_hi(u32 p) { return __uint_as_float(p & 0xFFFF0000u); }

// split pair (x0,x1) into hi/lo bf16x2
__device__ __forceinline__ void split2(float x0, float x1, u32& hi, u32& lo) {
    hi = pk_bf16(x0, x1);
    lo = pk_bf16(x0 - bf_lo(hi), x1 - bf_hi(hi));
}

// D(m16n8) += A(m16k16,bf16) * B(k16n8,bf16)
__device__ __forceinline__ void mma16(float d[4], const u32 a[4], const u32 b[2]) {
    asm volatile("mma.sync.aligned.m16n8k16.row.col.f32.bf16.bf16.f32 "
        "{%0,%1,%2,%3}, {%4,%5,%6,%7}, {%8,%9}, {%0,%1,%2,%3};"
        : "+f"(d[0]), "+f"(d[1]), "+f"(d[2]), "+f"(d[3])
        : "r"(a[0]), "r"(a[1]), "r"(a[2]), "r"(a[3]), "r"(b[0]), "r"(b[1]));
}

__global__ void __launch_bounds__(THREADS, 5)
edge_embed_bf16_kernel(const float* __restrict__ edge,
                       const float* __restrict__ adj,
                       const float* __restrict__ w4,
                       const float* __restrict__ w3,
                       float* __restrict__ out)
{
    __shared__ float adj_s[NN];      // 2 KB
    __shared__ float Sp[4][EE];      // per-warp partials
    __shared__ float Sh[EE];

    const int tid  = threadIdx.x;
    const int lane = tid & 31;
    const int warp = tid >> 5;
    const int gid  = lane >> 2;      // 0..7 (row group / n index)
    const int tig  = lane & 3;       // 0..3 (k pair index)
    const int row  = blockIdx.x;     // b*N + i

    const float* erow = edge + (size_t)row * (NN * FF);
    const float* arow = adj  + (size_t)row * NN;

    // stage adj row
    cp16(smem_u32(&adj_s[tid * 4]), arow + tid * 4);
    cpcommit();

    // ---- W4 fragments in registers, bf16 hi/lo split ----
    // B frag (k16n8): b0 = {W[n][2tig], W[n][2tig+1]}, b1 = {W[n][2tig+8], W[n][2tig+9]}
    u32 Whi[8][2], Wlo[8][2];
#pragma unroll
    for (int nt = 0; nt < 8; ++nt) {
        const int n = nt * 8 + gid;
        const float2* wv = reinterpret_cast<const float2*>(w4 + n * FF);
        float2 wl = __ldg(wv + tig);       // k = 2tig, 2tig+1
        float2 wh = __ldg(wv + tig + 4);   // k = 2tig+8, 2tig+9
        split2(wl.x, wl.y, Whi[nt][0], Wlo[nt][0]);
        split2(wh.x, wh.y, Whi[nt][1], Wlo[nt][1]);
    }

    u64 acc2[8];
#pragma unroll
    for (int i = 0; i < 8; ++i) acc2[i] = 0ULL;
    const u64 ABS2 = 0x7FFFFFFF7FFFFFFFULL;

    cpwait<0>();
    __syncthreads();

    // ---- main loop: 8 m-tiles (16 j each) per warp, E frags direct from global ----
#pragma unroll 2
    for (int i = 0; i < 8; ++i) {
        const int j0 = (warp * 8 + i) * 16;

        // A frag (m16k16): a0={E[gid][2tig..]}, a1={E[gid+8][2tig..]},
        //                  a2={E[gid][2tig+8..]}, a3={E[gid+8][2tig+8..]}
        const float2* e0 = reinterpret_cast<const float2*>(erow + (size_t)(j0 + gid) * FF);
        const float2* e1 = reinterpret_cast<const float2*>(erow + (size_t)(j0 + gid + 8) * FF);
        float2 x0 = __ldg(e0 + tig);
        float2 x1 = __ldg(e1 + tig);
        float2 x2 = __ldg(e0 + tig + 4);
        float2 x3 = __ldg(e1 + tig + 4);

        u32 Ahi[4], Alo[4];
        split2(x0.x, x0.y, Ahi[0], Alo[0]);
        split2(x1.x, x1.y, Ahi[1], Alo[1]);
        split2(x2.x, x2.y, Ahi[2], Alo[2]);
        split2(x3.x, x3.y, Ahi[3], Alo[3]);

        const float aj0 = adj_s[j0 + gid];
        const float aj1 = adj_s[j0 + gid + 8];
        const u64 A0 = pk2(aj0 * LR_A, aj0 * LR_A);
        const u64 B0 = pk2(aj0 * LR_B, aj0 * LR_B);
        const u64 A1 = pk2(aj1 * LR_A, aj1 * LR_A);
        const u64 B1 = pk2(aj1 * LR_B, aj1 * LR_B);

#pragma unroll
        for (int nt = 0; nt < 8; ++nt) {
            float d[4] = {0.f, 0.f, 0.f, 0.f};
            mma16(d, Ahi, Whi[nt]);   // hi * hi
            mma16(d, Alo, Whi[nt]);   // lo * hi
            mma16(d, Ahi, Wlo[nt]);   // hi * lo
            // d0,d1 -> (j0+gid, e=8nt+2tig{,+1}); d2,d3 -> (j0+gid+8, same e)
            u64 v01 = pk2(d[0], d[1]);
            u64 v23 = pk2(d[2], d[3]);
            acc2[nt] = ffma2(A0, v01,        acc2[nt]);
            acc2[nt] = ffma2(B0, v01 & ABS2, acc2[nt]);
            acc2[nt] = ffma2(A1, v23,        acc2[nt]);
            acc2[nt] = ffma2(B1, v23 & ABS2, acc2[nt]);
        }
    }

    // ---- reduce over gid (lanes differing by multiples of 4) ----
    float accf[16];
#pragma unroll
    for (int nt = 0; nt < 8; ++nt) upk2(acc2[nt], accf[2 * nt], accf[2 * nt + 1]);
#pragma unroll
    for (int off = 16; off >= 4; off >>= 1) {
#pragma unroll
        for (int i = 0; i < 16; ++i)
            accf[i] += __shfl_down_sync(0xFFFFFFFFu, accf[i], off);
    }
    if (lane < 4) {
#pragma unroll
        for (int nt = 0; nt < 8; ++nt) {
            Sp[warp][nt * 8 + 2 * lane]     = accf[2 * nt];
            Sp[warp][nt * 8 + 2 * lane + 1] = accf[2 * nt + 1];
        }
    }
    __syncthreads();

    if (tid < EE) {
        Sh[tid] = Sp[0][tid] + Sp[1][tid] + Sp[2][tid] + Sp[3][tid];
    }
    __syncthreads();

    // ---- theta3: out[row][o] = sum_e S[e] * w3[o][e] ----
    if (tid < EE) {
        const float4* w3v = reinterpret_cast<const float4*>(w3 + tid * EE);
        float o = 0.0f;
#pragma unroll
        for (int k = 0; k < 16; ++k) {
            float4 w = __ldg(w3v + k);
            o = fmaf(w.x, Sh[4 * k + 0], o);
            o = fmaf(w.y, Sh[4 * k + 1], o);
            o = fmaf(w.z, Sh[4 * k + 2], o);
            o = fmaf(w.w, Sh[4 * k + 3], o);
        }
        out[(size_t)row * EE + tid] = o;
    }
}

extern "C" void kernel_launch(void* const* d_in, const int* in_sizes, int n_in,
                              void* d_out, int out_size) {
    const float* edge = (const float*)d_in[0];   // (4,512,512,16) f32
    const float* adj  = (const float*)d_in[1];   // (4,512,512)    f32
    const float* w4   = (const float*)d_in[2];   // (64,16)        f32
    const float* w3   = (const float*)d_in[3];   // (64,64)        f32
    float* out = (float*)d_out;                  // (4,512,64)     f32

    edge_embed_bf16_kernel<<<BB * NN, THREADS>>>(edge, adj, w4, w3, out);
}

// round 9
// speedup vs baseline: 2.5764x; 1.0010x over previous
#include <cuda_runtime.h>
#include <cstdint>
#include <cstddef>

#define BB 4
#define NN 512
#define FF 16
#define EE 64
#define THREADS 128

#define LR_A 0.505f
#define LR_B 0.495f

typedef unsigned long long u64;
typedef unsigned int u32;

__device__ __forceinline__ u64 pk2(float lo, float hi) {
    u64 d; asm("mov.b64 %0, {%1, %2};" : "=l"(d) : "f"(lo), "f"(hi)); return d;
}
__device__ __forceinline__ void upk2(u64 v, float& lo, float& hi) {
    asm("mov.b64 {%0, %1}, %2;" : "=f"(lo), "=f"(hi) : "l"(v));
}
__device__ __forceinline__ u64 ffma2(u64 a, u64 b, u64 c) {
    u64 d; asm("fma.rn.f32x2 %0, %1, %2, %3;" : "=l"(d) : "l"(a), "l"(b), "l"(c)); return d;
}
__device__ __forceinline__ unsigned smem_u32(const void* p) {
    unsigned r;
    asm("{ .reg .u64 t; cvta.to.shared.u64 t, %1; cvt.u32.u64 %0, t; }" : "=r"(r) : "l"(p));
    return r;
}
__device__ __forceinline__ void cp16(unsigned d, const void* s) {
    asm volatile("cp.async.cg.shared.global [%0], [%1], 16;" :: "r"(d), "l"(s));
}
__device__ __forceinline__ void cpcommit() { asm volatile("cp.async.commit_group;" ::: "memory"); }
template <int N> __device__ __forceinline__ void cpwait() {
    asm volatile("cp.async.wait_group %0;" :: "n"(N) : "memory");
}

// pack two f32 -> bf16x2 (first arg -> low half)
__device__ __forceinline__ u32 pk_bf16(float lo, float hi) {
    u32 d; asm("cvt.rn.bf16x2.f32 %0, %1, %2;" : "=r"(d) : "f"(hi), "f"(lo)); return d;
}
__device__ __forceinline__ float bf_lo(u32 p) { return __uint_as_float(p << 16); }
__device__ __forceinline__ float bf_hi(u32 p) { return __uint_as_float(p & 0xFFFF0000u); }

__device__ __forceinline__ void split2(float x0, float x1, u32& hi, u32& lo) {
    hi = pk_bf16(x0, x1);
    lo = pk_bf16(x0 - bf_lo(hi), x1 - bf_hi(hi));
}

// D(m16n8) += A(m16k16,bf16) * B(k16n8,bf16)
__device__ __forceinline__ void mma16(float d[4], const u32 a[4], const u32 b[2]) {
    asm volatile("mma.sync.aligned.m16n8k16.row.col.f32.bf16.bf16.f32 "
        "{%0,%1,%2,%3}, {%4,%5,%6,%7}, {%8,%9}, {%0,%1,%2,%3};"
        : "+f"(d[0]), "+f"(d[1]), "+f"(d[2]), "+f"(d[3])
        : "r"(a[0]), "r"(a[1]), "r"(a[2]), "r"(a[3]), "r"(b[0]), "r"(b[1]));
}

__global__ void __launch_bounds__(THREADS, 5)
edge_embed_bf16_kernel(const float* __restrict__ edge,
                       const float* __restrict__ adj,
                       const float* __restrict__ w4,
                       const float* __restrict__ w3,
                       float* __restrict__ out)
{
    __shared__ float adj_s[NN];
    __shared__ float Sp[4][EE];
    __shared__ float Sh[EE];

    const int tid  = threadIdx.x;
    const int lane = tid & 31;
    const int warp = tid >> 5;
    const int gid  = lane >> 2;      // 0..7
    const int tig  = lane & 3;       // 0..3
    const int row  = blockIdx.x;     // b*N + i

    const float* erow = edge + (size_t)row * (NN * FF);
    const float* arow = adj  + (size_t)row * NN;

    cp16(smem_u32(&adj_s[tid * 4]), arow + tid * 4);
    cpcommit();

    // ---- W4 fragments (k-permuted): b0 = W[n][4tig,4tig+1], b1 = W[n][4tig+2,4tig+3]
    u32 Whi[8][2], Wlo[8][2];
#pragma unroll
    for (int nt = 0; nt < 8; ++nt) {
        const int n = nt * 8 + gid;
        float4 w = __ldg(reinterpret_cast<const float4*>(w4 + n * FF) + tig);
        split2(w.x, w.y, Whi[nt][0], Wlo[nt][0]);
        split2(w.z, w.w, Whi[nt][1], Wlo[nt][1]);
    }

    u64 acc2[8];
#pragma unroll
    for (int i = 0; i < 8; ++i) acc2[i] = 0ULL;
    const u64 ABS2 = 0x7FFFFFFF7FFFFFFFULL;

    cpwait<0>();
    __syncthreads();

    // A-frag source (k-permuted): one float4 per row (chunk tig of row j)
    const float4* ev = reinterpret_cast<const float4*>(erow);

    // prologue: first tile of THIS warp (j0 = warp*128)
    const int jbase = warp * 128;
    float4 x0 = __ldg(ev + (size_t)(jbase + gid) * 4 + tig);
    float4 x1 = __ldg(ev + (size_t)(jbase + gid + 8) * 4 + tig);

    // ---- main loop: 8 m-tiles (16 j each) per warp, software-pipelined loads ----
#pragma unroll
    for (int i = 0; i < 8; ++i) {
        const int j0 = jbase + i * 16;

        float4 c0 = x0, c1 = x1;
        if (i + 1 < 8) {
            const int jn = jbase + (i + 1) * 16;
            x0 = __ldg(ev + (size_t)(jn + gid) * 4 + tig);
            x1 = __ldg(ev + (size_t)(jn + gid + 8) * 4 + tig);
        }

        u32 Ahi[4], Alo[4];
        split2(c0.x, c0.y, Ahi[0], Alo[0]);   // a0: row gid,   k-slots 2tig..2tig+1
        split2(c1.x, c1.y, Ahi[1], Alo[1]);   // a1: row gid+8
        split2(c0.z, c0.w, Ahi[2], Alo[2]);   // a2: row gid,   k-slots 2tig+8..2tig+9
        split2(c1.z, c1.w, Ahi[3], Alo[3]);   // a3: row gid+8

        const float aj0 = adj_s[j0 + gid];
        const float aj1 = adj_s[j0 + gid + 8];
        const u64 A0 = pk2(aj0 * LR_A, aj0 * LR_A);
        const u64 B0 = pk2(aj0 * LR_B, aj0 * LR_B);
        const u64 A1 = pk2(aj1 * LR_A, aj1 * LR_A);
        const u64 B1 = pk2(aj1 * LR_B, aj1 * LR_B);

#pragma unroll
        for (int nt = 0; nt < 8; ++nt) {
            float d[4] = {0.f, 0.f, 0.f, 0.f};
            mma16(d, Ahi, Whi[nt]);
            mma16(d, Alo, Whi[nt]);
            mma16(d, Ahi, Wlo[nt]);
            u64 v01 = pk2(d[0], d[1]);
            u64 v23 = pk2(d[2], d[3]);
            acc2[nt] = ffma2(A0, v01,        acc2[nt]);
            acc2[nt] = ffma2(B0, v01 & ABS2, acc2[nt]);
            acc2[nt] = ffma2(A1, v23,        acc2[nt]);
            acc2[nt] = ffma2(B1, v23 & ABS2, acc2[nt]);
        }
    }

    // ---- reduce over gid (lanes differing by 4,8,16) ----
    float accf[16];
#pragma unroll
    for (int nt = 0; nt < 8; ++nt) upk2(acc2[nt], accf[2 * nt], accf[2 * nt + 1]);
#pragma unroll
    for (int off = 16; off >= 4; off >>= 1) {
#pragma unroll
        for (int i = 0; i < 16; ++i)
            accf[i] += __shfl_down_sync(0xFFFFFFFFu, accf[i], off);
    }
    if (lane < 4) {
#pragma unroll
        for (int nt = 0; nt < 8; ++nt) {
            Sp[warp][nt * 8 + 2 * lane]     = accf[2 * nt];
            Sp[warp][nt * 8 + 2 * lane + 1] = accf[2 * nt + 1];
        }
    }
    __syncthreads();

    if (tid < EE) {
        Sh[tid] = Sp[0][tid] + Sp[1][tid] + Sp[2][tid] + Sp[3][tid];
    }
    __syncthreads();

    // ---- theta3 ----
    if (tid < EE) {
        const float4* w3v = reinterpret_cast<const float4*>(w3 + tid * EE);
        float o = 0.0f;
#pragma unroll
        for (int k = 0; k < 16; ++k) {
            float4 w = __ldg(w3v + k);
            o = fmaf(w.x, Sh[4 * k + 0], o);
            o = fmaf(w.y, Sh[4 * k + 1], o);
            o = fmaf(w.z, Sh[4 * k + 2], o);
            o = fmaf(w.w, Sh[4 * k + 3], o);
        }
        out[(size_t)row * EE + tid] = o;
    }
}

extern "C" void kernel_launch(void* const* d_in, const int* in_sizes, int n_in,
                              void* d_out, int out_size) {
    const float* edge = (const float*)d_in[0];   // (4,512,512,16) f32
    const float* adj  = (const float*)d_in[1];   // (4,512,512)    f32
    const float* w4   = (const float*)d_in[2];   // (64,16)        f32
    const float* w3   = (const float*)d_in[3];   // (64,64)        f32
    float* out = (float*)d_out;                  // (4,512,64)     f32

    edge_embed_bf16_kernel<<<BB * NN, THREADS>>>(edge, adj, w4, w3, out);
}